// round 5
// baseline (speedup 1.0000x reference)
#include <cuda_runtime.h>

// ============================================================================
// SoftMesh MLP: [N,3] -> 50 -> 7x(50->50, tanh) -> 3
// Strategy: one thread per sample, all weights in dynamic SMEM (padded 50->52),
// inner products via packed fma.rn.f32x2 (FFMA2) with 26 independent
// accumulator chains, weights fetched as LDS.128 (warp-broadcast).
// ============================================================================

#define NHID   50
#define NPAD   52     // padded hidden width (even, 16B-aligned rows: 52*4=208B)
#define NJ2    26     // f32x2 pairs per row
#define NMID   7
#define TPB    256

// SMEM layout (in floats, all offsets multiples of 4 => 16B aligned)
#define OFF_WIN   0                      // [3][52]
#define OFF_BIN   156                    // [52]
#define OFF_WMID  208                    // [7][50][52]
#define OFF_BMID  (208 + 7*50*52)        // 18408: [7][52]
#define OFF_WOUT  (18408 + 7*52)         // 18772: [50][4] (3 used, 1 pad)
#define OFF_BOUT  (18772 + 50*4)         // 18972: [4]
#define SMEM_FLOATS (18972 + 4)          // 18976 floats
#define SMEM_BYTES  (SMEM_FLOATS * 4)    // 75904 bytes

__device__ __forceinline__ unsigned long long pack2(float lo, float hi) {
    unsigned long long r;
    asm("mov.b64 %0, {%1, %2};" : "=l"(r) : "f"(lo), "f"(hi));
    return r;
}

__device__ __forceinline__ void unpack2(unsigned long long v, float& lo, float& hi) {
    asm("mov.b64 {%0, %1}, %2;" : "=f"(lo), "=f"(hi) : "l"(v));
}

// Packed dual-FMA: d = a*b + c on 2 lanes of fp32 (FFMA2 in SASS; PTX-only form)
__device__ __forceinline__ unsigned long long ffma2(unsigned long long a,
                                                    unsigned long long b,
                                                    unsigned long long c) {
    unsigned long long d;
    asm("fma.rn.f32x2 %0, %1, %2, %3;" : "=l"(d) : "l"(a), "l"(b), "l"(c));
    return d;
}

// Accurate-enough tanh (abs err ~1e-7): tanh(x) = 1 - 2/(exp(2x)+1).
// Handles |x| large correctly (exp->inf => 1; exp->0 => -1).
__device__ __forceinline__ float fast_tanh(float x) {
    float e = __expf(2.0f * x);
    return 1.0f - __fdividef(2.0f, e + 1.0f);
}

extern __shared__ float smem[];

__global__ void __launch_bounds__(TPB)
softmesh_mlp_kernel(const float* __restrict__ x,
                    const float* __restrict__ y,
                    const float* __restrict__ z,
                    const float* __restrict__ W_in,   // [3,50]
                    const float* __restrict__ b_in,   // [50]
                    const float* __restrict__ W_mid,  // [7,50,50]
                    const float* __restrict__ b_mid,  // [7,50]
                    const float* __restrict__ W_out,  // [50,3]
                    const float* __restrict__ b_out,  // [3]
                    float* __restrict__ out,          // [3*N]: u0 | u1 | u2
                    int n) {
    const int tid = threadIdx.x;

    // ---- Stage weights into padded SMEM (zero padding first) ----
    for (int i = tid; i < SMEM_FLOATS; i += TPB) smem[i] = 0.0f;
    __syncthreads();

    for (int i = tid; i < 3 * NHID; i += TPB)
        smem[OFF_WIN + (i / NHID) * NPAD + (i % NHID)] = W_in[i];
    for (int i = tid; i < NHID; i += TPB)
        smem[OFF_BIN + i] = b_in[i];
    for (int i = tid; i < NMID * NHID * NHID; i += TPB) {
        int l = i / (NHID * NHID);
        int r = i % (NHID * NHID);
        int k = r / NHID;
        int j = r % NHID;
        smem[OFF_WMID + l * (NHID * NPAD) + k * NPAD + j] = W_mid[i];
    }
    for (int i = tid; i < NMID * NHID; i += TPB)
        smem[OFF_BMID + (i / NHID) * NPAD + (i % NHID)] = b_mid[i];
    for (int i = tid; i < NHID * 3; i += TPB)
        smem[OFF_WOUT + (i / 3) * 4 + (i % 3)] = W_out[i];
    if (tid < 3) smem[OFF_BOUT + tid] = b_out[tid];
    __syncthreads();

    const int gid = blockIdx.x * TPB + tid;
    if (gid >= n) return;

    // ---- Input layer: h = tanh([x,y,z] @ W_in + b_in) ----
    unsigned long long acc[NJ2];
    {
        const unsigned long long* bv =
            reinterpret_cast<const unsigned long long*>(smem + OFF_BIN);
#pragma unroll
        for (int j = 0; j < NJ2; j++) acc[j] = bv[j];

        const float xv = x[gid], yv = y[gid], zv = z[gid];
        const unsigned long long xd = pack2(xv, xv);
        const unsigned long long yd = pack2(yv, yv);
        const unsigned long long zd = pack2(zv, zv);

        const unsigned long long* w0 =
            reinterpret_cast<const unsigned long long*>(smem + OFF_WIN);
        const unsigned long long* w1 = w0 + NJ2;
        const unsigned long long* w2 = w0 + 2 * NJ2;
#pragma unroll
        for (int j = 0; j < NJ2; j++) acc[j] = ffma2(xd, w0[j], acc[j]);
#pragma unroll
        for (int j = 0; j < NJ2; j++) acc[j] = ffma2(yd, w1[j], acc[j]);
#pragma unroll
        for (int j = 0; j < NJ2; j++) acc[j] = ffma2(zd, w2[j], acc[j]);
    }

    float h[NPAD];
#pragma unroll
    for (int j = 0; j < NJ2; j++) {
        float lo, hi;
        unpack2(acc[j], lo, hi);
        h[2 * j]     = fast_tanh(lo);
        h[2 * j + 1] = fast_tanh(hi);
    }
    // padded lanes: b=0, W=0 => tanh(0)=0, and k-loop below uses only k<50.

    // ---- 7 mid layers: h = tanh(h @ W_mid[l] + b_mid[l]) ----
#pragma unroll 1
    for (int l = 0; l < NMID; l++) {
        const float* Wl = smem + OFF_WMID + l * (NHID * NPAD);
        const unsigned long long* bl =
            reinterpret_cast<const unsigned long long*>(smem + OFF_BMID + l * NPAD);
#pragma unroll
        for (int j = 0; j < NJ2; j++) acc[j] = bl[j];

#pragma unroll
        for (int k = 0; k < NHID; k++) {
            const unsigned long long hd = pack2(h[k], h[k]);
            const ulonglong2* row =
                reinterpret_cast<const ulonglong2*>(Wl + k * NPAD);
#pragma unroll
            for (int j = 0; j < NJ2 / 2; j++) {
                ulonglong2 w = row[j];                       // LDS.128, broadcast
                acc[2 * j]     = ffma2(hd, w.x, acc[2 * j]);
                acc[2 * j + 1] = ffma2(hd, w.y, acc[2 * j + 1]);
            }
        }

#pragma unroll
        for (int j = 0; j < NJ2; j++) {
            float lo, hi;
            unpack2(acc[j], lo, hi);
            h[2 * j]     = fast_tanh(lo);
            h[2 * j + 1] = fast_tanh(hi);
        }
    }

    // ---- Output layer: U = h @ W_out + b_out ----
    float u0 = smem[OFF_BOUT + 0];
    float u1 = smem[OFF_BOUT + 1];
    float u2 = smem[OFF_BOUT + 2];
#pragma unroll
    for (int k = 0; k < NHID; k++) {
        const float4 w = *reinterpret_cast<const float4*>(smem + OFF_WOUT + k * 4);
        u0 = fmaf(h[k], w.x, u0);
        u1 = fmaf(h[k], w.y, u1);
        u2 = fmaf(h[k], w.z, u2);
    }

    out[gid]         = u0;
    out[n + gid]     = u1;
    out[2 * n + gid] = u2;
}

extern "C" void kernel_launch(void* const* d_in, const int* in_sizes, int n_in,
                              void* d_out, int out_size) {
    const float* x     = (const float*)d_in[0];
    const float* y     = (const float*)d_in[1];
    const float* z     = (const float*)d_in[2];
    const float* W_in  = (const float*)d_in[3];
    const float* b_in  = (const float*)d_in[4];
    const float* W_mid = (const float*)d_in[5];
    const float* b_mid = (const float*)d_in[6];
    const float* W_out = (const float*)d_in[7];
    const float* b_out = (const float*)d_in[8];
    float* out = (float*)d_out;

    const int n = in_sizes[0];

    // Opt in to >48KB dynamic SMEM (idempotent; not a stream op, capture-safe).
    cudaFuncSetAttribute(softmesh_mlp_kernel,
                         cudaFuncAttributeMaxDynamicSharedMemorySize, SMEM_BYTES);

    const int blocks = (n + TPB - 1) / TPB;
    softmesh_mlp_kernel<<<blocks, TPB, SMEM_BYTES>>>(
        x, y, z, W_in, b_in, W_mid, b_mid, W_out, b_out, out, n);
}

// round 8
// speedup vs baseline: 1.5203x; 1.5203x over previous
#include <cuda_runtime.h>

// ============================================================================
// SoftMesh MLP: [N,3] -> 50 -> 7x(50->50, tanh) -> 3
// R5: 2 samples per thread. Each LDS.128 weight fetch now feeds 4 FFMA2
// (2 output-neuron pairs x 2 samples), halving the shared-memory wavefront
// traffic per sample that was the binding pipe (L1=78.6%) in R2's kernel.
// ============================================================================

#define NHID   50
#define NPAD   52     // padded hidden width (52*4 = 208B rows, 16B aligned)
#define NJ2    26     // f32x2 pairs per row
#define NMID   7
#define TPB    256

// SMEM layout (floats; offsets multiples of 4 => 16B aligned)
#define OFF_WIN   0                      // [3][52]
#define OFF_BIN   156                    // [52]
#define OFF_WMID  208                    // [7][50][52]
#define OFF_BMID  (208 + 7*50*52)        // 18408: [7][52]
#define OFF_WOUT  (18408 + 7*52)         // 18772: [50][4] (3 used, 1 pad)
#define OFF_BOUT  (18772 + 50*4)         // 18972: [4]
#define SMEM_FLOATS (18972 + 4)          // 18976 floats
#define SMEM_BYTES  (SMEM_FLOATS * 4)    // 75904 bytes

typedef unsigned long long ull;

__device__ __forceinline__ ull pack2(float lo, float hi) {
    ull r;
    asm("mov.b64 %0, {%1, %2};" : "=l"(r) : "f"(lo), "f"(hi));
    return r;
}

__device__ __forceinline__ void unpack2(ull v, float& lo, float& hi) {
    asm("mov.b64 {%0, %1}, %2;" : "=f"(lo), "=f"(hi) : "l"(v));
}

// Packed dual-FMA (FFMA2 in SASS; PTX-only form)
__device__ __forceinline__ ull ffma2(ull a, ull b, ull c) {
    ull d;
    asm("fma.rn.f32x2 %0, %1, %2, %3;" : "=l"(d) : "l"(a), "l"(b), "l"(c));
    return d;
}

// Accurate tanh (abs err ~1e-7): tanh(x) = 1 - 2/(exp(2x)+1).
__device__ __forceinline__ float fast_tanh(float x) {
    float e = __expf(2.0f * x);
    return 1.0f - __fdividef(2.0f, e + 1.0f);
}

extern __shared__ float smem[];

__global__ void __launch_bounds__(TPB)
softmesh_mlp_kernel(const float* __restrict__ x,
                    const float* __restrict__ y,
                    const float* __restrict__ z,
                    const float* __restrict__ W_in,   // [3,50]
                    const float* __restrict__ b_in,   // [50]
                    const float* __restrict__ W_mid,  // [7,50,50]
                    const float* __restrict__ b_mid,  // [7,50]
                    const float* __restrict__ W_out,  // [50,3]
                    const float* __restrict__ b_out,  // [3]
                    float* __restrict__ out,          // [3*N]: u0 | u1 | u2
                    int n) {
    const int tid = threadIdx.x;

    // ---- Stage weights into padded SMEM (zero padding first) ----
    for (int i = tid; i < SMEM_FLOATS; i += TPB) smem[i] = 0.0f;
    __syncthreads();

    for (int i = tid; i < 3 * NHID; i += TPB)
        smem[OFF_WIN + (i / NHID) * NPAD + (i % NHID)] = W_in[i];
    for (int i = tid; i < NHID; i += TPB)
        smem[OFF_BIN + i] = b_in[i];
    for (int i = tid; i < NMID * NHID * NHID; i += TPB) {
        int l = i / (NHID * NHID);
        int r = i % (NHID * NHID);
        int k = r / NHID;
        int j = r % NHID;
        smem[OFF_WMID + l * (NHID * NPAD) + k * NPAD + j] = W_mid[i];
    }
    for (int i = tid; i < NMID * NHID; i += TPB)
        smem[OFF_BMID + (i / NHID) * NPAD + (i % NHID)] = b_mid[i];
    for (int i = tid; i < NHID * 3; i += TPB)
        smem[OFF_WOUT + (i / 3) * 4 + (i % 3)] = W_out[i];
    if (tid < 3) smem[OFF_BOUT + tid] = b_out[tid];
    __syncthreads();

    // ---- 2 samples per thread: s0 in [0, half), s1 = s0 + half ----
    const int half = (n + 1) >> 1;
    const int gid = blockIdx.x * TPB + tid;
    if (gid >= half) return;
    const int s0 = gid;
    const int s1 = gid + half;
    const bool has1 = (s1 < n);
    const int s1c = has1 ? s1 : s0;   // clamp loads; stores guarded

    ull accA[NJ2], accB[NJ2];

    // ---- Input layer: h = tanh([x,y,z] @ W_in + b_in) ----
    {
        const ull* bv = reinterpret_cast<const ull*>(smem + OFF_BIN);
#pragma unroll
        for (int j = 0; j < NJ2; j++) { accA[j] = bv[j]; accB[j] = bv[j]; }

        const float x0 = x[s0], y0 = y[s0], z0 = z[s0];
        const float x1 = x[s1c], y1 = y[s1c], z1 = z[s1c];
        const ull xd0 = pack2(x0, x0), xd1 = pack2(x1, x1);
        const ull yd0 = pack2(y0, y0), yd1 = pack2(y1, y1);
        const ull zd0 = pack2(z0, z0), zd1 = pack2(z1, z1);

        const ull* w0 = reinterpret_cast<const ull*>(smem + OFF_WIN);
        const ull* w1 = w0 + NJ2;
        const ull* w2 = w0 + 2 * NJ2;
#pragma unroll
        for (int j = 0; j < NJ2; j++) {
            ull w = w0[j];
            accA[j] = ffma2(xd0, w, accA[j]);
            accB[j] = ffma2(xd1, w, accB[j]);
        }
#pragma unroll
        for (int j = 0; j < NJ2; j++) {
            ull w = w1[j];
            accA[j] = ffma2(yd0, w, accA[j]);
            accB[j] = ffma2(yd1, w, accB[j]);
        }
#pragma unroll
        for (int j = 0; j < NJ2; j++) {
            ull w = w2[j];
            accA[j] = ffma2(zd0, w, accA[j]);
            accB[j] = ffma2(zd1, w, accB[j]);
        }
    }

    float hA[NPAD], hB[NPAD];
#pragma unroll
    for (int j = 0; j < NJ2; j++) {
        float lo, hi;
        unpack2(accA[j], lo, hi);
        hA[2 * j]     = fast_tanh(lo);
        hA[2 * j + 1] = fast_tanh(hi);
        unpack2(accB[j], lo, hi);
        hB[2 * j]     = fast_tanh(lo);
        hB[2 * j + 1] = fast_tanh(hi);
    }

    // ---- 7 mid layers: h = tanh(h @ W_mid[l] + b_mid[l]) ----
#pragma unroll 1
    for (int l = 0; l < NMID; l++) {
        const ulonglong2* Wl = reinterpret_cast<const ulonglong2*>(
            smem + OFF_WMID + l * (NHID * NPAD));
        const ull* bl = reinterpret_cast<const ull*>(smem + OFF_BMID + l * NPAD);
#pragma unroll
        for (int j = 0; j < NJ2; j++) { accA[j] = bl[j]; accB[j] = bl[j]; }

        // Fully unrolled: keeps hA/hB/acc indices compile-time constant
        // (register-resident) and lets ptxas pipeline the LDS.128 stream.
#pragma unroll
        for (int k = 0; k < NHID; k++) {
            const ull hdA = pack2(hA[k], hA[k]);
            const ull hdB = pack2(hB[k], hB[k]);
            const ulonglong2* row = Wl + k * (NJ2 / 2);
#pragma unroll
            for (int jj = 0; jj < NJ2 / 2; jj++) {
                ulonglong2 w = row[jj];                 // LDS.128, warp-broadcast
                accA[2 * jj]     = ffma2(hdA, w.x, accA[2 * jj]);
                accB[2 * jj]     = ffma2(hdB, w.x, accB[2 * jj]);
                accA[2 * jj + 1] = ffma2(hdA, w.y, accA[2 * jj + 1]);
                accB[2 * jj + 1] = ffma2(hdB, w.y, accB[2 * jj + 1]);
            }
        }

#pragma unroll
        for (int j = 0; j < NJ2; j++) {
            float lo, hi;
            unpack2(accA[j], lo, hi);
            hA[2 * j]     = fast_tanh(lo);
            hA[2 * j + 1] = fast_tanh(hi);
            unpack2(accB[j], lo, hi);
            hB[2 * j]     = fast_tanh(lo);
            hB[2 * j + 1] = fast_tanh(hi);
        }
    }

    // ---- Output layer: U = h @ W_out + b_out ----
    float u0A = smem[OFF_BOUT + 0], u1A = smem[OFF_BOUT + 1], u2A = smem[OFF_BOUT + 2];
    float u0B = u0A, u1B = u1A, u2B = u2A;
#pragma unroll
    for (int k = 0; k < NHID; k++) {
        const float4 w = *reinterpret_cast<const float4*>(smem + OFF_WOUT + k * 4);
        u0A = fmaf(hA[k], w.x, u0A);
        u1A = fmaf(hA[k], w.y, u1A);
        u2A = fmaf(hA[k], w.z, u2A);
        u0B = fmaf(hB[k], w.x, u0B);
        u1B = fmaf(hB[k], w.y, u1B);
        u2B = fmaf(hB[k], w.z, u2B);
    }

    out[s0]         = u0A;
    out[n + s0]     = u1A;
    out[2 * n + s0] = u2A;
    if (has1) {
        out[s1]         = u0B;
        out[n + s1]     = u1B;
        out[2 * n + s1] = u2B;
    }
}

extern "C" void kernel_launch(void* const* d_in, const int* in_sizes, int n_in,
                              void* d_out, int out_size) {
    const float* x     = (const float*)d_in[0];
    const float* y     = (const float*)d_in[1];
    const float* z     = (const float*)d_in[2];
    const float* W_in  = (const float*)d_in[3];
    const float* b_in  = (const float*)d_in[4];
    const float* W_mid = (const float*)d_in[5];
    const float* b_mid = (const float*)d_in[6];
    const float* W_out = (const float*)d_in[7];
    const float* b_out = (const float*)d_in[8];
    float* out = (float*)d_out;

    const int n = in_sizes[0];
    const int half = (n + 1) >> 1;

    cudaFuncSetAttribute(softmesh_mlp_kernel,
                         cudaFuncAttributeMaxDynamicSharedMemorySize, SMEM_BYTES);

    const int blocks = (half + TPB - 1) / TPB;
    softmesh_mlp_kernel<<<blocks, TPB, SMEM_BYTES>>>(
        x, y, z, W_in, b_in, W_mid, b_mid, W_out, b_out, out, n);
}

// round 10
// speedup vs baseline: 2.4434x; 1.6072x over previous
#include <cuda_runtime.h>
#include <cuda_bf16.h>
#include <stdint.h>

// ============================================================================
// SoftMesh MLP: [N,3] -> 50 -> 7x(50->50 tanh) -> 3
// R9: warp-level mma.sync bf16 hi/lo split (compute_103-portable HMMA).
//  - Each warp owns 16 samples (m16). Activations live ONLY in registers:
//    the m16n8 f32 accumulator fragment of layer l is reinterpreted as the
//    m16k16 A-fragment of layer l+1 (two adjacent n8 tiles = one k16 tile).
//  - Weights pre-split into bf16 hi/lo and stored in SMEM in exact B-fragment
//    lane order: one LDS.128 per (ntile,ktile) yields {b0h,b1h,b0l,b1l}.
//  - D = Ah*Wh + Ah*Wl + Al*Wh (fp32 accum); bias via accumulator init.
//  - Hidden dim padded 50 -> 56 used cols (7 n-tiles), K = 64 (4 k-tiles,
//    rows >= 50 zeroed in the weight fragments).
// ============================================================================

#define NHID  50
#define NMID  7
#define TPB   384
#define WARPS (TPB / 32)     // 12
#define ITERS 4
#define SPC   (WARPS * 16 * ITERS)   // samples per CTA = 768

typedef uint32_t u32;

// SMEM byte offsets
#define SM_FRAG  0                         // [7][7nt][4kt][32 lanes] x 16B
#define FRAG_L   (7 * 4 * 32)              // ulonglong2 entries per layer = 896
#define SM_BIAS  (7 * FRAG_L * 16)         // 100352: [7][64] f32
#define SM_WIN   (SM_BIAS + 7 * 64 * 4)    // 102144: [3][64] f32
#define SM_BIN   (SM_WIN + 3 * 64 * 4)     // 102912: [64] f32
#define SM_WOUT  (SM_BIN + 64 * 4)         // 103168: [64][4] f32
#define SM_BOUT  (SM_WOUT + 64 * 4 * 4)    // 104192: [4] f32
#define SMEM_BYTES (SM_BOUT + 16)          // 104208

__device__ __forceinline__ float fast_tanh(float x) {
    float e = __expf(2.0f * x);
    return 1.0f - __fdividef(2.0f, e + 1.0f);
}

// pack two f32 -> bf16x2: low half = f0, high half = f1
__device__ __forceinline__ u32 bf2(float f0, float f1) {
    u32 r;
    asm("cvt.rn.bf16x2.f32 %0, %1, %2;" : "=r"(r) : "f"(f1), "f"(f0));
    return r;
}

// hi = bf16 round of (f0,f1); lo = residual pair, also bf16
__device__ __forceinline__ void make_ahl(float f0, float f1, u32& hi, u32& lo) {
    u32 hw = bf2(f0, f1);
    float h0 = __uint_as_float(hw << 16);
    float h1 = __uint_as_float(hw & 0xffff0000u);
    hi = hw;
    lo = bf2(f0 - h0, f1 - h1);
}

__device__ __forceinline__ void mma16816(float* c, const u32* a, u32 b0, u32 b1) {
    asm volatile(
        "mma.sync.aligned.m16n8k16.row.col.f32.bf16.bf16.f32 "
        "{%0,%1,%2,%3}, {%4,%5,%6,%7}, {%8,%9}, {%0,%1,%2,%3};"
        : "+f"(c[0]), "+f"(c[1]), "+f"(c[2]), "+f"(c[3])
        : "r"(a[0]), "r"(a[1]), "r"(a[2]), "r"(a[3]), "r"(b0), "r"(b1));
}

extern __shared__ char smem[];

__global__ void __launch_bounds__(TPB)
softmesh_mma_kernel(const float* __restrict__ x,
                    const float* __restrict__ y,
                    const float* __restrict__ z,
                    const float* __restrict__ W_in,   // [3,50]
                    const float* __restrict__ b_in,   // [50]
                    const float* __restrict__ W_mid,  // [7,50,50]
                    const float* __restrict__ b_mid,  // [7,50]
                    const float* __restrict__ W_out,  // [50,3]
                    const float* __restrict__ b_out,  // [3]
                    float* __restrict__ out,          // [3N]
                    int n) {
    const int tid = threadIdx.x;

    // ---------------- Build weight fragments in SMEM ----------------
    // B-fragment (m16n8k16, col-major KxN): lane q=lane&3, nl=lane>>2.
    //   b0 = {W[k0][n], W[k0+1][n]},  b1 = {W[k0+8][n], W[k0+9][n]},
    //   k0 = 16*kt + 2*q, n = 8*nt + nl.
    // Entry = ulonglong2 { x = {b0h, b1h}, y = {b0l, b1l} }.
    {
        ulonglong2* frag = (ulonglong2*)(smem + SM_FRAG);
        for (int i = tid; i < NMID * FRAG_L; i += TPB) {
            int lane = i & 31;
            int kt = (i >> 5) & 3;
            int nt = (i >> 7) % 7;
            int l  = i / FRAG_L;
            int q = lane & 3, nl = lane >> 2;
            int nn = nt * 8 + nl;
            int k0 = kt * 16 + q * 2;
            float w[4];
#pragma unroll
            for (int j = 0; j < 4; j++) {
                int k = k0 + (j >> 1) * 8 + (j & 1);
                w[j] = (k < NHID && nn < NHID)
                     ? W_mid[(l * NHID + k) * NHID + nn] : 0.0f;
            }
            u32 b0h, b0l, b1h, b1l;
            make_ahl(w[0], w[1], b0h, b0l);
            make_ahl(w[2], w[3], b1h, b1l);
            ulonglong2 e;
            e.x = ((unsigned long long)b1h << 32) | b0h;
            e.y = ((unsigned long long)b1l << 32) | b0l;
            frag[i] = e;
        }
        float* bias = (float*)(smem + SM_BIAS);
        for (int i = tid; i < NMID * 64; i += TPB) {
            int l = i >> 6, c = i & 63;
            bias[i] = (c < NHID) ? b_mid[l * NHID + c] : 0.0f;
        }
        float* win = (float*)(smem + SM_WIN);
        for (int i = tid; i < 3 * 64; i += TPB) {
            int r = i >> 6, c = i & 63;
            win[i] = (c < NHID) ? W_in[r * NHID + c] : 0.0f;
        }
        float* bin = (float*)(smem + SM_BIN);
        for (int i = tid; i < 64; i += TPB)
            bin[i] = (i < NHID) ? b_in[i] : 0.0f;
        float* wout = (float*)(smem + SM_WOUT);
        for (int i = tid; i < 64 * 4; i += TPB) {
            int c = i >> 2, j = i & 3;
            wout[i] = (c < NHID && j < 3) ? W_out[c * 3 + j] : 0.0f;
        }
        if (tid < 3) ((float*)(smem + SM_BOUT))[tid] = b_out[tid];
    }
    __syncthreads();

    const int warp = tid >> 5;
    const int lane = tid & 31;
    const int q = lane & 3;
    const int r = lane >> 2;          // row 0..7 within m16 tile

    const float* win  = (const float*)(smem + SM_WIN);
    const float* bin  = (const float*)(smem + SM_BIN);
    const float* bias = (const float*)(smem + SM_BIAS);
    const float* wout = (const float*)(smem + SM_WOUT);
    const ulonglong2* frag = (const ulonglong2*)(smem + SM_FRAG);

#pragma unroll 1
    for (int it = 0; it < ITERS; it++) {
        const int base = blockIdx.x * SPC + it * (WARPS * 16) + warp * 16;
        const int s0 = base + r;          // row r
        const int s1 = base + r + 8;      // row r+8
        const int s0c = (s0 < n) ? s0 : (n - 1);
        const int s1c = (s1 < n) ? s1 : (n - 1);

        const float x0 = x[s0c], y0 = y[s0c], z0 = z[s0c];
        const float x1 = x[s1c], y1 = y[s1c], z1 = z[s1c];

        u32 ah[4][4], al[4][4];

        // ---------------- Input layer (scalar) -> A fragments ----------------
        // h(row, c) = tanh(b_in[c] + x*Win0[c] + y*Win1[c] + z*Win2[c]), c<50.
#pragma unroll
        for (int kt = 0; kt < 4; kt++) {
#pragma unroll
            for (int half = 0; half < 2; half++) {        // half=0: k0.. ; 1: k0+8
                int c0 = kt * 16 + q * 2 + half * 8;
                float t00 = 0.0f, t01 = 0.0f, t10 = 0.0f, t11 = 0.0f;
                if (c0 < NHID) {
                    float p0 = fmaf(x0, win[c0], bin[c0]);
                    p0 = fmaf(y0, win[64 + c0], p0);
                    p0 = fmaf(z0, win[128 + c0], p0);
                    t00 = fast_tanh(p0);
                    float p1 = fmaf(x1, win[c0], bin[c0]);
                    p1 = fmaf(y1, win[64 + c0], p1);
                    p1 = fmaf(z1, win[128 + c0], p1);
                    t10 = fast_tanh(p1);
                }
                if (c0 + 1 < NHID) {
                    int c1 = c0 + 1;
                    float p0 = fmaf(x0, win[c1], bin[c1]);
                    p0 = fmaf(y0, win[64 + c1], p0);
                    p0 = fmaf(z0, win[128 + c1], p0);
                    t01 = fast_tanh(p0);
                    float p1 = fmaf(x1, win[c1], bin[c1]);
                    p1 = fmaf(y1, win[64 + c1], p1);
                    p1 = fmaf(z1, win[128 + c1], p1);
                    t11 = fast_tanh(p1);
                }
                make_ahl(t00, t01, ah[kt][0 + 2 * half], al[kt][0 + 2 * half]);
                make_ahl(t10, t11, ah[kt][1 + 2 * half], al[kt][1 + 2 * half]);
            }
        }

        float t[7][4];

        // ---------------- 7 mid layers via HMMA ----------------
#pragma unroll 1
        for (int l = 0; l < NMID; l++) {
            float c[7][4];
#pragma unroll
            for (int nt = 0; nt < 7; nt++) {
                int col0 = nt * 8 + q * 2;
                float bv0 = bias[l * 64 + col0];
                float bv1 = bias[l * 64 + col0 + 1];
                c[nt][0] = bv0; c[nt][1] = bv1;
                c[nt][2] = bv0; c[nt][3] = bv1;
            }
            const ulonglong2* fl = frag + l * FRAG_L;
#pragma unroll
            for (int nt = 0; nt < 7; nt++) {
#pragma unroll
                for (int kt = 0; kt < 4; kt++) {
                    ulonglong2 B = fl[(nt * 4 + kt) * 32 + lane];  // LDS.128
                    u32 b0h = (u32)B.x, b1h = (u32)(B.x >> 32);
                    u32 b0l = (u32)B.y, b1l = (u32)(B.y >> 32);
                    mma16816(c[nt], ah[kt], b0h, b1h);
                    mma16816(c[nt], ah[kt], b0l, b1l);
                    mma16816(c[nt], al[kt], b0h, b1h);
                }
            }
            // epilogue: tanh + repack accumulators as next layer's A fragments
#pragma unroll
            for (int nt = 0; nt < 7; nt++) {
#pragma unroll
                for (int j = 0; j < 4; j++) t[nt][j] = fast_tanh(c[nt][j]);
            }
            if (l == NMID - 1) break;
#pragma unroll
            for (int kt = 0; kt < 4; kt++) {
                int nt0 = 2 * kt;
                make_ahl(t[nt0][0], t[nt0][1], ah[kt][0], al[kt][0]);
                make_ahl(t[nt0][2], t[nt0][3], ah[kt][1], al[kt][1]);
                if (kt < 3) {
                    int nt1 = nt0 + 1;
                    make_ahl(t[nt1][0], t[nt1][1], ah[kt][2], al[kt][2]);
                    make_ahl(t[nt1][2], t[nt1][3], ah[kt][3], al[kt][3]);
                } else {
                    ah[kt][2] = ah[kt][3] = 0u;   // cols 56..63: weights are 0
                    al[kt][2] = al[kt][3] = 0u;
                }
            }
        }

        // ---------------- Output layer: U = h @ W_out + b_out ----------------
        float u00 = 0.0f, u01 = 0.0f, u02 = 0.0f;   // row r
        float u10 = 0.0f, u11 = 0.0f, u12 = 0.0f;   // row r+8
#pragma unroll
        for (int nt = 0; nt < 7; nt++) {
            int col0 = nt * 8 + q * 2;
            const float4 w0 = *(const float4*)(wout + col0 * 4);       // col0 (0 if >=50)
            const float4 w1 = *(const float4*)(wout + (col0 + 1) * 4); // col0+1
            u00 = fmaf(t[nt][0], w0.x, u00); u00 = fmaf(t[nt][1], w1.x, u00);
            u01 = fmaf(t[nt][0], w0.y, u01); u01 = fmaf(t[nt][1], w1.y, u01);
            u02 = fmaf(t[nt][0], w0.z, u02); u02 = fmaf(t[nt][1], w1.z, u02);
            u10 = fmaf(t[nt][2], w0.x, u10); u10 = fmaf(t[nt][3], w1.x, u10);
            u11 = fmaf(t[nt][2], w0.y, u11); u11 = fmaf(t[nt][3], w1.y, u11);
            u12 = fmaf(t[nt][2], w0.z, u12); u12 = fmaf(t[nt][3], w1.z, u12);
        }
        // reduce across the 4 q-lanes of each row
#pragma unroll
        for (int off = 1; off <= 2; off <<= 1) {
            u00 += __shfl_xor_sync(0xffffffffu, u00, off);
            u01 += __shfl_xor_sync(0xffffffffu, u01, off);
            u02 += __shfl_xor_sync(0xffffffffu, u02, off);
            u10 += __shfl_xor_sync(0xffffffffu, u10, off);
            u11 += __shfl_xor_sync(0xffffffffu, u11, off);
            u12 += __shfl_xor_sync(0xffffffffu, u12, off);
        }
        if (q == 0) {
            const float b0v = ((const float*)(smem + SM_BOUT))[0];
            const float b1v = ((const float*)(smem + SM_BOUT))[1];
            const float b2v = ((const float*)(smem + SM_BOUT))[2];
            if (s0 < n) {
                out[s0]         = u00 + b0v;
                out[n + s0]     = u01 + b1v;
                out[2 * n + s0] = u02 + b2v;
            }
            if (s1 < n) {
                out[s1]         = u10 + b0v;
                out[n + s1]     = u11 + b1v;
                out[2 * n + s1] = u12 + b2v;
            }
        }
    }
}

extern "C" void kernel_launch(void* const* d_in, const int* in_sizes, int n_in,
                              void* d_out, int out_size) {
    const float* x     = (const float*)d_in[0];
    const float* y     = (const float*)d_in[1];
    const float* z     = (const float*)d_in[2];
    const float* W_in  = (const float*)d_in[3];
    const float* b_in  = (const float*)d_in[4];
    const float* W_mid = (const float*)d_in[5];
    const float* b_mid = (const float*)d_in[6];
    const float* W_out = (const float*)d_in[7];
    const float* b_out = (const float*)d_in[8];
    float* out = (float*)d_out;

    const int n = in_sizes[0];

    cudaFuncSetAttribute(softmesh_mma_kernel,
                         cudaFuncAttributeMaxDynamicSharedMemorySize, SMEM_BYTES);

    const int blocks = (n + SPC - 1) / SPC;
    softmesh_mma_kernel<<<blocks, TPB, SMEM_BYTES>>>(
        x, y, z, W_in, b_in, W_mid, b_mid, W_out, b_out, out, n);
}

// round 12
// speedup vs baseline: 2.7593x; 1.1292x over previous
#include <cuda_runtime.h>
#include <cuda_bf16.h>
#include <stdint.h>

// ============================================================================
// SoftMesh MLP: [N,3] -> 50 -> 7x(50->50 tanh) -> 3
// R10 = R9 (warp mma.sync bf16 hi/lo split, register-resident activations)
//  + __launch_bounds__(384, 2): cap regs at 85 so TWO CTAs fit the 64K
//    register file -> 24 warps/SM (R9 was reg-limited to 1 CTA / 12 warps,
//    issue=50% latency-bound).
//  + ITERS 4 -> 8: halves per-CTA weight-fragment build overhead (4.4 waves).
// ============================================================================

#define NHID  50
#define NMID  7
#define TPB   384
#define WARPS (TPB / 32)     // 12
#define ITERS 8
#define SPC   (WARPS * 16 * ITERS)   // samples per CTA = 1536

typedef uint32_t u32;

// SMEM byte offsets
#define SM_FRAG  0                         // [7][7nt][4kt][32 lanes] x 16B
#define FRAG_L   (7 * 4 * 32)              // ulonglong2 entries per layer = 896
#define SM_BIAS  (7 * FRAG_L * 16)         // 100352: [7][64] f32
#define SM_WIN   (SM_BIAS + 7 * 64 * 4)    // 102144: [3][64] f32
#define SM_BIN   (SM_WIN + 3 * 64 * 4)     // 102912: [64] f32
#define SM_WOUT  (SM_BIN + 64 * 4)         // 103168: [64][4] f32
#define SM_BOUT  (SM_WOUT + 64 * 4 * 4)    // 104192: [4] f32
#define SMEM_BYTES (SM_BOUT + 16)          // 104208  (x2 CTAs = 208KB < 228KB)

__device__ __forceinline__ float fast_tanh(float x) {
    float e = __expf(2.0f * x);
    return 1.0f - __fdividef(2.0f, e + 1.0f);
}

// pack two f32 -> bf16x2: low half = f0, high half = f1
__device__ __forceinline__ u32 bf2(float f0, float f1) {
    u32 r;
    asm("cvt.rn.bf16x2.f32 %0, %1, %2;" : "=r"(r) : "f"(f1), "f"(f0));
    return r;
}

// hi = bf16 round of (f0,f1); lo = residual pair, also bf16
__device__ __forceinline__ void make_ahl(float f0, float f1, u32& hi, u32& lo) {
    u32 hw = bf2(f0, f1);
    float h0 = __uint_as_float(hw << 16);
    float h1 = __uint_as_float(hw & 0xffff0000u);
    hi = hw;
    lo = bf2(f0 - h0, f1 - h1);
}

__device__ __forceinline__ void mma16816(float* c, const u32* a, u32 b0, u32 b1) {
    asm volatile(
        "mma.sync.aligned.m16n8k16.row.col.f32.bf16.bf16.f32 "
        "{%0,%1,%2,%3}, {%4,%5,%6,%7}, {%8,%9}, {%0,%1,%2,%3};"
        : "+f"(c[0]), "+f"(c[1]), "+f"(c[2]), "+f"(c[3])
        : "r"(a[0]), "r"(a[1]), "r"(a[2]), "r"(a[3]), "r"(b0), "r"(b1));
}

extern __shared__ char smem[];

__global__ void __launch_bounds__(TPB, 2)
softmesh_mma_kernel(const float* __restrict__ x,
                    const float* __restrict__ y,
                    const float* __restrict__ z,
                    const float* __restrict__ W_in,   // [3,50]
                    const float* __restrict__ b_in,   // [50]
                    const float* __restrict__ W_mid,  // [7,50,50]
                    const float* __restrict__ b_mid,  // [7,50]
                    const float* __restrict__ W_out,  // [50,3]
                    const float* __restrict__ b_out,  // [3]
                    float* __restrict__ out,          // [3N]
                    int n) {
    const int tid = threadIdx.x;

    // ---------------- Build weight fragments in SMEM ----------------
    // B-fragment (m16n8k16, col-major KxN): lane q=lane&3, nl=lane>>2.
    //   b0 = {W[k0][n], W[k0+1][n]},  b1 = {W[k0+8][n], W[k0+9][n]},
    //   k0 = 16*kt + 2*q, n = 8*nt + nl.
    // Entry = ulonglong2 { x = {b0h, b1h}, y = {b0l, b1l} }.
    {
        ulonglong2* frag = (ulonglong2*)(smem + SM_FRAG);
        for (int i = tid; i < NMID * FRAG_L; i += TPB) {
            int lane = i & 31;
            int kt = (i >> 5) & 3;
            int nt = (i >> 7) % 7;
            int l  = i / FRAG_L;
            int q = lane & 3, nl = lane >> 2;
            int nn = nt * 8 + nl;
            int k0 = kt * 16 + q * 2;
            float w[4];
#pragma unroll
            for (int j = 0; j < 4; j++) {
                int k = k0 + (j >> 1) * 8 + (j & 1);
                w[j] = (k < NHID && nn < NHID)
                     ? W_mid[(l * NHID + k) * NHID + nn] : 0.0f;
            }
            u32 b0h, b0l, b1h, b1l;
            make_ahl(w[0], w[1], b0h, b0l);
            make_ahl(w[2], w[3], b1h, b1l);
            ulonglong2 e;
            e.x = ((unsigned long long)b1h << 32) | b0h;
            e.y = ((unsigned long long)b1l << 32) | b0l;
            frag[i] = e;
        }
        float* bias = (float*)(smem + SM_BIAS);
        for (int i = tid; i < NMID * 64; i += TPB) {
            int l = i >> 6, c = i & 63;
            bias[i] = (c < NHID) ? b_mid[l * NHID + c] : 0.0f;
        }
        float* win = (float*)(smem + SM_WIN);
        for (int i = tid; i < 3 * 64; i += TPB) {
            int r = i >> 6, c = i & 63;
            win[i] = (c < NHID) ? W_in[r * NHID + c] : 0.0f;
        }
        float* bin = (float*)(smem + SM_BIN);
        for (int i = tid; i < 64; i += TPB)
            bin[i] = (i < NHID) ? b_in[i] : 0.0f;
        float* wout = (float*)(smem + SM_WOUT);
        for (int i = tid; i < 64 * 4; i += TPB) {
            int c = i >> 2, j = i & 3;
            wout[i] = (c < NHID && j < 3) ? W_out[c * 3 + j] : 0.0f;
        }
        if (tid < 3) ((float*)(smem + SM_BOUT))[tid] = b_out[tid];
    }
    __syncthreads();

    const int warp = tid >> 5;
    const int lane = tid & 31;
    const int q = lane & 3;
    const int r = lane >> 2;          // row 0..7 within m16 tile

    const float* win  = (const float*)(smem + SM_WIN);
    const float* bin  = (const float*)(smem + SM_BIN);
    const float* bias = (const float*)(smem + SM_BIAS);
    const float* wout = (const float*)(smem + SM_WOUT);
    const ulonglong2* frag = (const ulonglong2*)(smem + SM_FRAG);

#pragma unroll 1
    for (int it = 0; it < ITERS; it++) {
        const int base = blockIdx.x * SPC + it * (WARPS * 16) + warp * 16;
        const int s0 = base + r;          // row r
        const int s1 = base + r + 8;      // row r+8
        const int s0c = (s0 < n) ? s0 : (n - 1);
        const int s1c = (s1 < n) ? s1 : (n - 1);

        const float x0 = x[s0c], y0 = y[s0c], z0 = z[s0c];
        const float x1 = x[s1c], y1 = y[s1c], z1 = z[s1c];

        u32 ah[4][4], al[4][4];

        // ---------------- Input layer (scalar) -> A fragments ----------------
        // h(row, c) = tanh(b_in[c] + x*Win0[c] + y*Win1[c] + z*Win2[c]), c<50.
#pragma unroll
        for (int kt = 0; kt < 4; kt++) {
#pragma unroll
            for (int half = 0; half < 2; half++) {        // half=0: k0.. ; 1: k0+8
                int c0 = kt * 16 + q * 2 + half * 8;
                float t00 = 0.0f, t01 = 0.0f, t10 = 0.0f, t11 = 0.0f;
                if (c0 < NHID) {
                    float p0 = fmaf(x0, win[c0], bin[c0]);
                    p0 = fmaf(y0, win[64 + c0], p0);
                    p0 = fmaf(z0, win[128 + c0], p0);
                    t00 = fast_tanh(p0);
                    float p1 = fmaf(x1, win[c0], bin[c0]);
                    p1 = fmaf(y1, win[64 + c0], p1);
                    p1 = fmaf(z1, win[128 + c0], p1);
                    t10 = fast_tanh(p1);
                }
                if (c0 + 1 < NHID) {
                    int c1 = c0 + 1;
                    float p0 = fmaf(x0, win[c1], bin[c1]);
                    p0 = fmaf(y0, win[64 + c1], p0);
                    p0 = fmaf(z0, win[128 + c1], p0);
                    t01 = fast_tanh(p0);
                    float p1 = fmaf(x1, win[c1], bin[c1]);
                    p1 = fmaf(y1, win[64 + c1], p1);
                    p1 = fmaf(z1, win[128 + c1], p1);
                    t11 = fast_tanh(p1);
                }
                make_ahl(t00, t01, ah[kt][0 + 2 * half], al[kt][0 + 2 * half]);
                make_ahl(t10, t11, ah[kt][1 + 2 * half], al[kt][1 + 2 * half]);
            }
        }

        float t[7][4];

        // ---------------- 7 mid layers via HMMA ----------------
#pragma unroll 1
        for (int l = 0; l < NMID; l++) {
            float c[7][4];
#pragma unroll
            for (int nt = 0; nt < 7; nt++) {
                int col0 = nt * 8 + q * 2;
                float bv0 = bias[l * 64 + col0];
                float bv1 = bias[l * 64 + col0 + 1];
                c[nt][0] = bv0; c[nt][1] = bv1;
                c[nt][2] = bv0; c[nt][3] = bv1;
            }
            const ulonglong2* fl = frag + l * FRAG_L;
#pragma unroll
            for (int nt = 0; nt < 7; nt++) {
#pragma unroll
                for (int kt = 0; kt < 4; kt++) {
                    ulonglong2 B = fl[(nt * 4 + kt) * 32 + lane];  // LDS.128
                    u32 b0h = (u32)B.x, b1h = (u32)(B.x >> 32);
                    u32 b0l = (u32)B.y, b1l = (u32)(B.y >> 32);
                    mma16816(c[nt], ah[kt], b0h, b1h);
                    mma16816(c[nt], ah[kt], b0l, b1l);
                    mma16816(c[nt], al[kt], b0h, b1h);
                }
            }
            // epilogue: tanh + repack accumulators as next layer's A fragments
#pragma unroll
            for (int nt = 0; nt < 7; nt++) {
#pragma unroll
                for (int j = 0; j < 4; j++) t[nt][j] = fast_tanh(c[nt][j]);
            }
            if (l == NMID - 1) break;
#pragma unroll
            for (int kt = 0; kt < 4; kt++) {
                int nt0 = 2 * kt;
                make_ahl(t[nt0][0], t[nt0][1], ah[kt][0], al[kt][0]);
                make_ahl(t[nt0][2], t[nt0][3], ah[kt][1], al[kt][1]);
                if (kt < 3) {
                    int nt1 = nt0 + 1;
                    make_ahl(t[nt1][0], t[nt1][1], ah[kt][2], al[kt][2]);
                    make_ahl(t[nt1][2], t[nt1][3], ah[kt][3], al[kt][3]);
                } else {
                    ah[kt][2] = ah[kt][3] = 0u;   // cols 56..63: weights are 0
                    al[kt][2] = al[kt][3] = 0u;
                }
            }
        }

        // ---------------- Output layer: U = h @ W_out + b_out ----------------
        float u00 = 0.0f, u01 = 0.0f, u02 = 0.0f;   // row r
        float u10 = 0.0f, u11 = 0.0f, u12 = 0.0f;   // row r+8
#pragma unroll
        for (int nt = 0; nt < 7; nt++) {
            int col0 = nt * 8 + q * 2;
            const float4 w0 = *(const float4*)(wout + col0 * 4);       // col0 (0 if >=50)
            const float4 w1 = *(const float4*)(wout + (col0 + 1) * 4); // col0+1
            u00 = fmaf(t[nt][0], w0.x, u00); u00 = fmaf(t[nt][1], w1.x, u00);
            u01 = fmaf(t[nt][0], w0.y, u01); u01 = fmaf(t[nt][1], w1.y, u01);
            u02 = fmaf(t[nt][0], w0.z, u02); u02 = fmaf(t[nt][1], w1.z, u02);
            u10 = fmaf(t[nt][2], w0.x, u10); u10 = fmaf(t[nt][3], w1.x, u10);
            u11 = fmaf(t[nt][2], w0.y, u11); u11 = fmaf(t[nt][3], w1.y, u11);
            u12 = fmaf(t[nt][2], w0.z, u12); u12 = fmaf(t[nt][3], w1.z, u12);
        }
        // reduce across the 4 q-lanes of each row
#pragma unroll
        for (int off = 1; off <= 2; off <<= 1) {
            u00 += __shfl_xor_sync(0xffffffffu, u00, off);
            u01 += __shfl_xor_sync(0xffffffffu, u01, off);
            u02 += __shfl_xor_sync(0xffffffffu, u02, off);
            u10 += __shfl_xor_sync(0xffffffffu, u10, off);
            u11 += __shfl_xor_sync(0xffffffffu, u11, off);
            u12 += __shfl_xor_sync(0xffffffffu, u12, off);
        }
        if (q == 0) {
            const float b0v = ((const float*)(smem + SM_BOUT))[0];
            const float b1v = ((const float*)(smem + SM_BOUT))[1];
            const float b2v = ((const float*)(smem + SM_BOUT))[2];
            if (s0 < n) {
                out[s0]         = u00 + b0v;
                out[n + s0]     = u01 + b1v;
                out[2 * n + s0] = u02 + b2v;
            }
            if (s1 < n) {
                out[s1]         = u10 + b0v;
                out[n + s1]     = u11 + b1v;
                out[2 * n + s1] = u12 + b2v;
            }
        }
    }
}

extern "C" void kernel_launch(void* const* d_in, const int* in_sizes, int n_in,
                              void* d_out, int out_size) {
    const float* x     = (const float*)d_in[0];
    const float* y     = (const float*)d_in[1];
    const float* z     = (const float*)d_in[2];
    const float* W_in  = (const float*)d_in[3];
    const float* b_in  = (const float*)d_in[4];
    const float* W_mid = (const float*)d_in[5];
    const float* b_mid = (const float*)d_in[6];
    const float* W_out = (const float*)d_in[7];
    const float* b_out = (const float*)d_in[8];
    float* out = (float*)d_out;

    const int n = in_sizes[0];

    cudaFuncSetAttribute(softmesh_mma_kernel,
                         cudaFuncAttributeMaxDynamicSharedMemorySize, SMEM_BYTES);

    const int blocks = (n + SPC - 1) / SPC;
    softmesh_mma_kernel<<<blocks, TPB, SMEM_BYTES>>>(
        x, y, z, W_in, b_in, W_mid, b_mid, W_out, b_out, out, n);
}